// round 14
// baseline (speedup 1.0000x reference)
#include <cuda_runtime.h>
#include <math.h>

typedef unsigned long long u64;

#define BB 8
#define NN 2048
#define MM 2048
#define NC 32        // chunks along reduced dim
#define CW 64        // chunk width
#define FEPS 1e-12f
#define L2E 1.4426950408889634f

// ---------------- scratch (device globals; no allocs allowed) ----------------
__device__ float g_invt[BB];
__device__ float g_minsq[BB][NC][NN];
__device__ float g_colpart[BB][NC][MM];
__device__ float g_part6[BB][NC][6][NN];
__device__ float g_hpart[BB][8][16];
__device__ unsigned g_cnt[BB];    // finalize last-block counter (mod-8 parity)
__device__ unsigned g_cnt_a[BB];  // alpha last-block counter (mod-128 parity)

// ---------------- f32x2 + MUFU helpers ----------------
__device__ __forceinline__ u64 pk2(float lo, float hi) {
    u64 r; asm("mov.b64 %0,{%1,%2};" : "=l"(r) : "f"(lo), "f"(hi)); return r;
}
__device__ __forceinline__ void upk2(float& lo, float& hi, u64 v) {
    asm("mov.b64 {%0,%1},%2;" : "=f"(lo), "=f"(hi) : "l"(v));
}
__device__ __forceinline__ u64 fma2(u64 a, u64 b, u64 c) {
    u64 d; asm("fma.rn.f32x2 %0,%1,%2,%3;" : "=l"(d) : "l"(a), "l"(b), "l"(c)); return d;
}
__device__ __forceinline__ u64 add2(u64 a, u64 b) {
    u64 d; asm("add.rn.f32x2 %0,%1,%2;" : "=l"(d) : "l"(a), "l"(b)); return d;
}
__device__ __forceinline__ u64 mul2(u64 a, u64 b) {
    u64 d; asm("mul.rn.f32x2 %0,%1,%2;" : "=l"(d) : "l"(a), "l"(b)); return d;
}
__device__ __forceinline__ float fsqrt_a(float x) {
    float r; asm("sqrt.approx.f32 %0,%1;" : "=f"(r) : "f"(x)); return r;
}
__device__ __forceinline__ float fex2(float x) {
    float r; asm("ex2.approx.f32 %0,%1;" : "=f"(r) : "f"(x)); return r;
}
__device__ __forceinline__ float frcp_a(float x) {
    float r; asm("rcp.approx.f32 %0,%1;" : "=f"(r) : "f"(x)); return r;
}

// One MUFU op for TWO exponentials at f16 precision (~5e-4 rel).
// Used only for the gamma weight term (feeds R,t via 3x3 SVD — insensitive).
__device__ __forceinline__ u64 ex2_f16pair(float a0, float a1) {
    unsigned p;
    asm("{\n\t"
        ".reg .f16x2 t;\n\t"
        "cvt.rn.f16x2.f32 t, %1, %2;\n\t"   // hi = a1, lo = a0
        "ex2.approx.f16x2 t, t;\n\t"
        "mov.b32 %0, t;\n\t"
        "}" : "=r"(p) : "f"(a1), "f"(a0));
    float lo, hi;
    asm("{\n\t"
        ".reg .f16 l, h;\n\t"
        "mov.b32 {l, h}, %2;\n\t"
        "cvt.f32.f16 %0, l;\n\t"
        "cvt.f32.f16 %1, h;\n\t"
        "}" : "=f"(lo), "=f"(hi) : "r"(p));
    return pk2(lo, hi);
}

// ---------------- K1: alpha partial min + (last block per batch) combine ----------------
// grid (4 ntile, 32 mchunk, 8 b), 256 threads; thread owns n0 = nt*512+tid, n1 = n0+256.
__global__ void k_alpha_part(const float* __restrict__ src) {
    int b = blockIdx.z, nt = blockIdx.x, mc = blockIdx.y, tid = threadIdx.x;
    int n0 = nt * 512 + tid, n1 = n0 + 256;
    int mb = mc * CW;
    const float* S = src + b * 3 * NN;
    __shared__ ulonglong2 t_xy[CW];
    __shared__ ulonglong2 t_zw[CW];
    if (tid < CW) {
        int m = mb + tid;
        float x = S[m], y = S[NN + m], z = S[2 * NN + m];
        float w = x * x + y * y + z * z;
        t_xy[tid] = make_ulonglong2(pk2(x, x), pk2(y, y));
        t_zw[tid] = make_ulonglong2(pk2(z, z), pk2(w, w));
    }
    float x0 = S[n0], y0 = S[NN + n0], z0 = S[2 * NN + n0];
    float x1 = S[n1], y1 = S[NN + n1], z1 = S[2 * NN + n1];
    u64 X = pk2(-2.f * x0, -2.f * x1), Y = pk2(-2.f * y0, -2.f * y1), Z = pk2(-2.f * z0, -2.f * z1);
    u64 P = pk2(x0 * x0 + y0 * y0 + z0 * z0, x1 * x1 + y1 * y1 + z1 * z1);
    int jd0 = n0 - mb, jd1 = n1 - mb;   // diagonal hit only if in [0,CW)
    __syncthreads();
    float mn0 = 1e30f, mn1 = 1e30f;
    // Diag can hit at most one of the two n's (they differ by 256 > CW).
    bool has_diag = ((unsigned)jd0 < CW) || ((unsigned)jd1 < CW);
    if (has_diag) {
#pragma unroll 8
        for (int j = 0; j < CW; j++) {
            ulonglong2 xy = t_xy[j], zw = t_zw[j];
            u64 sq = fma2(X, xy.x, fma2(Y, xy.y, fma2(Z, zw.x, add2(P, zw.y))));
            float s0, s1;
            upk2(s0, s1, sq);
            if (j == jd0) s0 = 1e30f;
            if (j == jd1) s1 = 1e30f;
            mn0 = fminf(mn0, s0);
            mn1 = fminf(mn1, s1);
        }
    } else {
#pragma unroll 8
        for (int j = 0; j < CW; j++) {
            ulonglong2 xy = t_xy[j], zw = t_zw[j];
            u64 sq = fma2(X, xy.x, fma2(Y, xy.y, fma2(Z, zw.x, add2(P, zw.y))));
            float s0, s1;
            upk2(s0, s1, sq);
            mn0 = fminf(mn0, s0);
            mn1 = fminf(mn1, s1);
        }
    }
    g_minsq[b][mc][n0] = mn0;
    g_minsq[b][mc][n1] = mn1;

    // ---- last block per batch combines to invt (128 blocks per b) ----
    __shared__ unsigned s_last;
    __syncthreads();
    if (tid == 0) {
        __threadfence();
        unsigned old = atomicAdd(&g_cnt_a[b], 1u);
        s_last = ((old & 127u) == 127u) ? 1u : 0u;
    }
    __syncthreads();
    if (!s_last) return;
    __threadfence();
    float s = 0.0f;
    for (int n = tid; n < NN; n += 256) {
        float mn = 1e30f;
#pragma unroll
        for (int c = 0; c < NC; c++) mn = fminf(mn, g_minsq[b][c][n]);
        s += fsqrt_a(fmaxf(mn, FEPS));
    }
    __shared__ float red[256];
    red[tid] = s; __syncthreads();
    for (int st = 128; st > 0; st >>= 1) {
        if (tid < st) red[tid] += red[tid + st];
        __syncthreads();
    }
    if (tid == 0) {
        float alpha = red[0] * (1.0f / (float)NN);
        g_invt[b] = 1.0f / (4.0f * alpha);
    }
}

// ---------------- K3: column softmax denominators (packed pair, MUFU exp) ----------------
// grid (4 mtile, 32 nchunk, 8 b), 256 threads; thread owns m0, m0+256.
__global__ void k_colsum_part(const float* __restrict__ src, const float* __restrict__ tgt) {
    int b = blockIdx.z, mt = blockIdx.x, nc = blockIdx.y, tid = threadIdx.x;
    int m0 = mt * 512 + tid, m1 = m0 + 256;
    int nb = nc * CW;
    const float* S = src + b * 3 * NN;
    const float* T = tgt + b * 3 * MM;
    __shared__ ulonglong2 t_xy[CW];
    __shared__ ulonglong2 t_zw[CW];
    if (tid < CW) {
        int m = nb + tid;
        float x = S[m], y = S[NN + m], z = S[2 * NN + m];
        float w = x * x + y * y + z * z;
        t_xy[tid] = make_ulonglong2(pk2(x, x), pk2(y, y));
        t_zw[tid] = make_ulonglong2(pk2(z, z), pk2(w, w));
    }
    float x0 = T[m0], y0 = T[MM + m0], z0 = T[2 * MM + m0];
    float x1 = T[m1], y1 = T[MM + m1], z1 = T[2 * MM + m1];
    u64 X = pk2(-2.f * x0, -2.f * x1), Y = pk2(-2.f * y0, -2.f * y1), Z = pk2(-2.f * z0, -2.f * z1);
    u64 P = pk2(x0 * x0 + y0 * y0 + z0 * z0, x1 * x1 + y1 * y1 + z1 * z1);
    float c1 = -g_invt[b] * L2E;
    __syncthreads();
    float a0 = 0.f, a1 = 0.f;
#pragma unroll 8
    for (int j = 0; j < CW; j++) {
        ulonglong2 xy = t_xy[j], zw = t_zw[j];
        u64 sq = fma2(X, xy.x, fma2(Y, xy.y, fma2(Z, zw.x, add2(P, zw.y))));
        float s0, s1;
        upk2(s0, s1, sq);
        a0 += fex2(fsqrt_a(fmaxf(s0, FEPS)) * c1);
        a1 += fex2(fsqrt_a(fmaxf(s1, FEPS)) * c1);
    }
    g_colpart[b][nc][m0] = a0;
    g_colpart[b][nc][m1] = a1;
}

// ---------------- K4: main pass partials (e on f32 MUFU, h on f16x2 MUFU) ----------------
// grid (4 ntile, 32 mchunk, 8 b), 256 threads; thread owns n0, n0+256.
__global__ void k_main_part(const float* __restrict__ src, const float* __restrict__ tgt,
                            const int* __restrict__ iter) {
    int b = blockIdx.z, nt = blockIdx.x, mc = blockIdx.y, tid = threadIdx.x;
    int n0 = nt * 512 + tid, n1 = n0 + 256;
    int mb = mc * CW;
    const float* S = src + b * 3 * NN;
    const float* T = tgt + b * 3 * MM;
    __shared__ ulonglong2 t_xy[CW];
    __shared__ ulonglong2 t_zw[CW];
    __shared__ u64 t_ic[CW];
    if (tid < CW) {
        int m = mb + tid;
        float x = T[m], y = T[MM + m], z = T[2 * MM + m];
        float w = x * x + y * y + z * z;
        t_xy[tid] = make_ulonglong2(pk2(x, x), pk2(y, y));
        t_zw[tid] = make_ulonglong2(pk2(z, z), pk2(w, w));
        float cs = 0.0f;
#pragma unroll
        for (int nc = 0; nc < NC; nc++) cs += g_colpart[b][nc][m];
        float ic = frcp_a(cs);
        t_ic[tid] = pk2(ic, ic);
    }
    float x0 = S[n0], y0 = S[NN + n0], z0 = S[2 * NN + n0];
    float x1 = S[n1], y1 = S[NN + n1], z1 = S[2 * NN + n1];
    u64 X = pk2(-2.f * x0, -2.f * x1), Y = pk2(-2.f * y0, -2.f * y1), Z = pk2(-2.f * z0, -2.f * z1);
    u64 P = pk2(x0 * x0 + y0 * y0 + z0 * z0, x1 * x1 + y1 * y1 + z1 * z1);
    float c1 = -g_invt[b] * L2E;
    float invT = fex2((float)(*iter - 1));      // 1/T = 2^(iter-1)
    float ch = 2.0f * c1 - invT * L2E;          // e^2 * f = exp2(ch * d)
    __syncthreads();
    u64 R = 0, Sv = 0, G = 0, C0a = 0, C1a = 0, C2a = 0;
#pragma unroll 4
    for (int j = 0; j < CW; j++) {
        ulonglong2 xy = t_xy[j], zw = t_zw[j];
        u64 ic = t_ic[j];
        u64 sq = fma2(X, xy.x, fma2(Y, xy.y, fma2(Z, zw.x, add2(P, zw.y))));
        float q0, q1;
        upk2(q0, q1, sq);
        float d0 = fsqrt_a(fmaxf(q0, FEPS));
        float d1 = fsqrt_a(fmaxf(q1, FEPS));
        float e0 = fex2(d0 * c1), e1 = fex2(d1 * c1);    // softmax numerator (f32 MUFU)
        u64 h2 = ex2_f16pair(d0 * ch, d1 * ch);          // e^2*exp(-d/T), one f16x2 MUFU
        u64 e2 = pk2(e0, e1);
        u64 w = mul2(mul2(e2, e2), ic);
        R = add2(R, e2);
        Sv = add2(Sv, w);
        G = fma2(h2, ic, G);
        C0a = fma2(w, xy.x, C0a);
        C1a = fma2(w, xy.y, C1a);
        C2a = fma2(w, zw.x, C2a);
    }
    float v0, v1;
    upk2(v0, v1, R);   g_part6[b][mc][0][n0] = v0; g_part6[b][mc][0][n1] = v1;
    upk2(v0, v1, Sv);  g_part6[b][mc][1][n0] = v0; g_part6[b][mc][1][n1] = v1;
    upk2(v0, v1, G);   g_part6[b][mc][2][n0] = v0; g_part6[b][mc][2][n1] = v1;
    upk2(v0, v1, C0a); g_part6[b][mc][3][n0] = v0; g_part6[b][mc][3][n1] = v1;
    upk2(v0, v1, C1a); g_part6[b][mc][4][n0] = v0; g_part6[b][mc][4][n1] = v1;
    upk2(v0, v1, C2a); g_part6[b][mc][5][n0] = v0; g_part6[b][mc][5][n1] = v1;
}

// ---------------- 3x3 Procrustes SVD (double, one thread) ----------------
__device__ void svd3_kabsch(const double H[3][3], double R[3][3]) {
    double A[3][3];
    for (int i = 0; i < 3; i++)
        for (int j = 0; j < 3; j++) {
            double s = 0;
            for (int k = 0; k < 3; k++) s += H[k][i] * H[k][j];
            A[i][j] = s;
        }
    double V[3][3] = {{1,0,0},{0,1,0},{0,0,1}};
    const int PQ[3][2] = {{0,1},{0,2},{1,2}};
    for (int sweep = 0; sweep < 30; sweep++) {
        double off = fabs(A[0][1]) + fabs(A[0][2]) + fabs(A[1][2]);
        if (off < 1e-30) break;
        for (int r = 0; r < 3; r++) {
            int p = PQ[r][0], q = PQ[r][1];
            double apq = A[p][q];
            if (fabs(apq) < 1e-300) continue;
            double theta = (A[q][q] - A[p][p]) / (2.0 * apq);
            double t = ((theta >= 0.0) ? 1.0 : -1.0) / (fabs(theta) + sqrt(1.0 + theta * theta));
            double c = 1.0 / sqrt(1.0 + t * t), s = t * c;
            for (int k = 0; k < 3; k++) {
                double akp = A[k][p], akq = A[k][q];
                A[k][p] = c * akp - s * akq;
                A[k][q] = s * akp + c * akq;
            }
            for (int k = 0; k < 3; k++) {
                double apk = A[p][k], aqk = A[q][k];
                A[p][k] = c * apk - s * aqk;
                A[q][k] = s * apk + c * aqk;
            }
            for (int k = 0; k < 3; k++) {
                double vkp = V[k][p], vkq = V[k][q];
                V[k][p] = c * vkp - s * vkq;
                V[k][q] = s * vkp + c * vkq;
            }
        }
    }
    int idx[3] = {0, 1, 2};
    double lam[3] = {A[0][0], A[1][1], A[2][2]};
    for (int i = 0; i < 2; i++)
        for (int j = i + 1; j < 3; j++)
            if (lam[idx[j]] > lam[idx[i]]) { int t = idx[i]; idx[i] = idx[j]; idx[j] = t; }
    double U[3][3], Vs[3][3];
    for (int i = 0; i < 3; i++) {
        int id = idx[i];
        double v0 = V[0][id], v1 = V[1][id], v2 = V[2][id];
        double u0 = H[0][0]*v0 + H[0][1]*v1 + H[0][2]*v2;
        double u1 = H[1][0]*v0 + H[1][1]*v1 + H[1][2]*v2;
        double u2 = H[2][0]*v0 + H[2][1]*v1 + H[2][2]*v2;
        double sig = sqrt(u0*u0 + u1*u1 + u2*u2);
        sig = (sig > 1e-300) ? sig : 1e-300;
        U[0][i] = u0 / sig; U[1][i] = u1 / sig; U[2][i] = u2 / sig;
        Vs[0][i] = v0; Vs[1][i] = v1; Vs[2][i] = v2;
    }
    double detH = H[0][0]*(H[1][1]*H[2][2] - H[1][2]*H[2][1])
                - H[0][1]*(H[1][0]*H[2][2] - H[1][2]*H[2][0])
                + H[0][2]*(H[1][0]*H[2][1] - H[1][1]*H[2][0]);
    double flip = (detH < 0.0) ? -1.0 : 1.0;
    Vs[0][2] *= flip; Vs[1][2] *= flip; Vs[2][2] *= flip;
    for (int r = 0; r < 3; r++)
        for (int c = 0; c < 3; c++)
            R[r][c] = Vs[r][0]*U[c][0] + Vs[r][1]*U[c][1] + Vs[r][2]*U[c][2];
}

// ---------------- K5: finalize per-n + H partials + (last block per batch) SVD ----------------
// grid (8 ntile, 8 b), 256 threads. out: [0,72) R, [72,96) t, [96,...) src_corr
__global__ void k_finalize(const float* __restrict__ src, float* __restrict__ out) {
    int nt = blockIdx.x, b = blockIdx.y, tid = threadIdx.x;
    int n = nt * 256 + tid;
    const float* S = src + b * 3 * NN;
    float* corr = out + 96 + b * 3 * NN;
    float Rn = 0.f, S2 = 0.f, G = 0.f, c0 = 0.f, c1 = 0.f, c2 = 0.f;
#pragma unroll 8
    for (int mc = 0; mc < NC; mc++) {
        Rn += g_part6[b][mc][0][n];
        S2 += g_part6[b][mc][1][n];
        G  += g_part6[b][mc][2][n];
        c0 += g_part6[b][mc][3][n];
        c1 += g_part6[b][mc][4][n];
        c2 += g_part6[b][mc][5][n];
    }
    float g = G / Rn;
    float invden = 1.0f / (S2 + FEPS * Rn);
    float cx = c0 * invden, cy = c1 * invden, cz = c2 * invden;
    corr[n]          = cx;
    corr[NN + n]     = cy;
    corr[2 * NN + n] = cz;
    float sx = S[n], sy = S[NN + n], sz = S[2 * NN + n];
    float acc[16];
    acc[0] = g;
    acc[1] = g * sx;  acc[2] = g * sy;  acc[3] = g * sz;
    acc[4] = g * cx;  acc[5] = g * cy;  acc[6] = g * cz;
    acc[7]  = g * sx * cx; acc[8]  = g * sx * cy; acc[9]  = g * sx * cz;
    acc[10] = g * sy * cx; acc[11] = g * sy * cy; acc[12] = g * sy * cz;
    acc[13] = g * sz * cx; acc[14] = g * sz * cy; acc[15] = g * sz * cz;
    __shared__ float red[256];
    for (int k = 0; k < 16; k++) {
        red[tid] = acc[k]; __syncthreads();
        for (int st = 128; st > 0; st >>= 1) {
            if (tid < st) red[tid] += red[tid + st];
            __syncthreads();
        }
        if (tid == 0) g_hpart[b][nt][k] = red[0];
        __syncthreads();
    }
    // Last block per batch (mod-8 parity: no counter reset needed across graph replays)
    if (tid != 0) return;
    __threadfence();
    unsigned old = atomicAdd(&g_cnt[b], 1u);
    if ((old & 7u) != 7u) return;
    __threadfence();
    float tot[16];
#pragma unroll
    for (int k = 0; k < 16; k++) {
        float s = 0.f;
#pragma unroll
        for (int t8 = 0; t8 < 8; t8++) s += g_hpart[b][t8][k];
        tot[k] = s;
    }
    double g1 = tot[0];
    double Ss[3] = {tot[1], tot[2], tot[3]};
    double Sc[3] = {tot[4], tot[5], tot[6]};
    double Mm[3][3] = {{tot[7], tot[8], tot[9]},
                       {tot[10], tot[11], tot[12]},
                       {tot[13], tot[14], tot[15]}};
    double gsum = g1 + 1e-12;
    double sm[3], cm[3];
    for (int d = 0; d < 3; d++) { sm[d] = Ss[d] / gsum; cm[d] = Sc[d] / gsum; }
    double H[3][3];
    for (int r = 0; r < 3; r++)
        for (int c = 0; c < 3; c++)
            H[r][c] = Mm[r][c] - sm[r] * Sc[c] - cm[c] * Ss[r] + sm[r] * cm[c] * g1;
    H[0][0] += 1e-12; H[1][1] += 2e-12; H[2][2] += 3e-12;
    double R3[3][3];
    svd3_kabsch(H, R3);
    for (int r = 0; r < 3; r++)
        for (int c = 0; c < 3; c++)
            out[b * 9 + r * 3 + c] = (float)R3[r][c];
    for (int d = 0; d < 3; d++)
        out[72 + b * 3 + d] =
            (float)(-(R3[d][0] * sm[0] + R3[d][1] * sm[1] + R3[d][2] * sm[2]) + cm[d]);
}

// ---------------- launch ----------------
extern "C" void kernel_launch(void* const* d_in, const int* in_sizes, int n_in,
                              void* d_out, int out_size) {
    const float* src = (const float*)d_in[0];
    const float* tgt = (const float*)d_in[1];
    const int* iter = (const int*)d_in[2];
    float* out = (float*)d_out;

    k_alpha_part<<<dim3(4, NC, 8), 256>>>(src);
    k_colsum_part<<<dim3(4, NC, 8), 256>>>(src, tgt);
    k_main_part<<<dim3(4, NC, 8), 256>>>(src, tgt, iter);
    k_finalize<<<dim3(8, 8), 256>>>(src, out);
}

// round 15
// speedup vs baseline: 1.0516x; 1.0516x over previous
#include <cuda_runtime.h>
#include <math.h>

typedef unsigned long long u64;

#define BB 8
#define NN 2048
#define MM 2048
#define NC 32        // chunks along reduced dim
#define CW 64        // chunk width
#define FEPS 1e-12f
#define L2E 1.4426950408889634f

// ---------------- scratch (device globals; no allocs allowed) ----------------
__device__ float g_invt[BB];
__device__ float g_minsq[BB][NC][NN];
__device__ float g_colpart[BB][NC][MM];
__device__ float g_part6[BB][NC][6][NN];
__device__ float g_hpart[BB][32][16];
__device__ unsigned g_cnt[BB];    // finalize last-block counter (mod-32 parity)

// ---------------- f32x2 + MUFU helpers ----------------
__device__ __forceinline__ u64 pk2(float lo, float hi) {
    u64 r; asm("mov.b64 %0,{%1,%2};" : "=l"(r) : "f"(lo), "f"(hi)); return r;
}
__device__ __forceinline__ void upk2(float& lo, float& hi, u64 v) {
    asm("mov.b64 {%0,%1},%2;" : "=f"(lo), "=f"(hi) : "l"(v));
}
__device__ __forceinline__ u64 fma2(u64 a, u64 b, u64 c) {
    u64 d; asm("fma.rn.f32x2 %0,%1,%2,%3;" : "=l"(d) : "l"(a), "l"(b), "l"(c)); return d;
}
__device__ __forceinline__ u64 add2(u64 a, u64 b) {
    u64 d; asm("add.rn.f32x2 %0,%1,%2;" : "=l"(d) : "l"(a), "l"(b)); return d;
}
__device__ __forceinline__ u64 mul2(u64 a, u64 b) {
    u64 d; asm("mul.rn.f32x2 %0,%1,%2;" : "=l"(d) : "l"(a), "l"(b)); return d;
}
__device__ __forceinline__ float fsqrt_a(float x) {
    float r; asm("sqrt.approx.f32 %0,%1;" : "=f"(r) : "f"(x)); return r;
}
__device__ __forceinline__ float fex2(float x) {
    float r; asm("ex2.approx.f32 %0,%1;" : "=f"(r) : "f"(x)); return r;
}
__device__ __forceinline__ float frcp_a(float x) {
    float r; asm("rcp.approx.f32 %0,%1;" : "=f"(r) : "f"(x)); return r;
}

// One MUFU op for TWO exponentials at f16 precision (~5e-4 rel).
// Used only for the gamma weight term (feeds R,t via 3x3 SVD — insensitive).
__device__ __forceinline__ u64 ex2_f16pair(float a0, float a1) {
    unsigned p;
    asm("{\n\t"
        ".reg .f16x2 t;\n\t"
        "cvt.rn.f16x2.f32 t, %1, %2;\n\t"   // hi = a1, lo = a0
        "ex2.approx.f16x2 t, t;\n\t"
        "mov.b32 %0, t;\n\t"
        "}" : "=r"(p) : "f"(a1), "f"(a0));
    float lo, hi;
    asm("{\n\t"
        ".reg .f16 l, h;\n\t"
        "mov.b32 {l, h}, %2;\n\t"
        "cvt.f32.f16 %0, l;\n\t"
        "cvt.f32.f16 %1, h;\n\t"
        "}" : "=f"(lo), "=f"(hi) : "r"(p));
    return pk2(lo, hi);
}

// ---------------- K1: alpha partial min (packed pair, diag-split) ----------------
// grid (4 ntile, 32 mchunk, 8 b), 256 threads; thread owns n0 = nt*512+tid, n1 = n0+256.
__global__ void k_alpha_part(const float* __restrict__ src) {
    int b = blockIdx.z, nt = blockIdx.x, mc = blockIdx.y, tid = threadIdx.x;
    int n0 = nt * 512 + tid, n1 = n0 + 256;
    int mb = mc * CW;
    const float* S = src + b * 3 * NN;
    __shared__ ulonglong2 t_xy[CW];
    __shared__ ulonglong2 t_zw[CW];
    if (tid < CW) {
        int m = mb + tid;
        float x = S[m], y = S[NN + m], z = S[2 * NN + m];
        float w = x * x + y * y + z * z;
        t_xy[tid] = make_ulonglong2(pk2(x, x), pk2(y, y));
        t_zw[tid] = make_ulonglong2(pk2(z, z), pk2(w, w));
    }
    float x0 = S[n0], y0 = S[NN + n0], z0 = S[2 * NN + n0];
    float x1 = S[n1], y1 = S[NN + n1], z1 = S[2 * NN + n1];
    u64 X = pk2(-2.f * x0, -2.f * x1), Y = pk2(-2.f * y0, -2.f * y1), Z = pk2(-2.f * z0, -2.f * z1);
    u64 P = pk2(x0 * x0 + y0 * y0 + z0 * z0, x1 * x1 + y1 * y1 + z1 * z1);
    int jd0 = n0 - mb, jd1 = n1 - mb;   // diagonal hit only if in [0,CW)
    __syncthreads();
    float mn0 = 1e30f, mn1 = 1e30f;
    bool has_diag = ((unsigned)jd0 < CW) || ((unsigned)jd1 < CW);
    if (has_diag) {
#pragma unroll 8
        for (int j = 0; j < CW; j++) {
            ulonglong2 xy = t_xy[j], zw = t_zw[j];
            u64 sq = fma2(X, xy.x, fma2(Y, xy.y, fma2(Z, zw.x, add2(P, zw.y))));
            float s0, s1;
            upk2(s0, s1, sq);
            if (j == jd0) s0 = 1e30f;
            if (j == jd1) s1 = 1e30f;
            mn0 = fminf(mn0, s0);
            mn1 = fminf(mn1, s1);
        }
    } else {
#pragma unroll 8
        for (int j = 0; j < CW; j++) {
            ulonglong2 xy = t_xy[j], zw = t_zw[j];
            u64 sq = fma2(X, xy.x, fma2(Y, xy.y, fma2(Z, zw.x, add2(P, zw.y))));
            float s0, s1;
            upk2(s0, s1, sq);
            mn0 = fminf(mn0, s0);
            mn1 = fminf(mn1, s1);
        }
    }
    g_minsq[b][mc][n0] = mn0;
    g_minsq[b][mc][n1] = mn1;
}

// ---------------- K2: combine alpha -> invt ----------------
__global__ void k_alpha_comb() {
    int b = blockIdx.x, tid = threadIdx.x;
    __shared__ float red[256];
    float s = 0.0f;
    for (int n = tid; n < NN; n += 256) {
        float mn = 1e30f;
#pragma unroll
        for (int mc = 0; mc < NC; mc++) mn = fminf(mn, g_minsq[b][mc][n]);
        s += fsqrt_a(fmaxf(mn, FEPS));
    }
    red[tid] = s; __syncthreads();
    for (int st = 128; st > 0; st >>= 1) {
        if (tid < st) red[tid] += red[tid + st];
        __syncthreads();
    }
    if (tid == 0) {
        float alpha = red[0] * (1.0f / (float)NN);
        g_invt[b] = 1.0f / (4.0f * alpha);
    }
}

// ---------------- K3: column softmax denominators (packed pair, MUFU exp) ----------------
// grid (4 mtile, 32 nchunk, 8 b), 256 threads; thread owns m0, m0+256.
__global__ void k_colsum_part(const float* __restrict__ src, const float* __restrict__ tgt) {
    int b = blockIdx.z, mt = blockIdx.x, nc = blockIdx.y, tid = threadIdx.x;
    int m0 = mt * 512 + tid, m1 = m0 + 256;
    int nb = nc * CW;
    const float* S = src + b * 3 * NN;
    const float* T = tgt + b * 3 * MM;
    __shared__ ulonglong2 t_xy[CW];
    __shared__ ulonglong2 t_zw[CW];
    if (tid < CW) {
        int m = nb + tid;
        float x = S[m], y = S[NN + m], z = S[2 * NN + m];
        float w = x * x + y * y + z * z;
        t_xy[tid] = make_ulonglong2(pk2(x, x), pk2(y, y));
        t_zw[tid] = make_ulonglong2(pk2(z, z), pk2(w, w));
    }
    float x0 = T[m0], y0 = T[MM + m0], z0 = T[2 * MM + m0];
    float x1 = T[m1], y1 = T[MM + m1], z1 = T[2 * MM + m1];
    u64 X = pk2(-2.f * x0, -2.f * x1), Y = pk2(-2.f * y0, -2.f * y1), Z = pk2(-2.f * z0, -2.f * z1);
    u64 P = pk2(x0 * x0 + y0 * y0 + z0 * z0, x1 * x1 + y1 * y1 + z1 * z1);
    float c1 = -g_invt[b] * L2E;
    __syncthreads();
    float a0 = 0.f, a1 = 0.f;
#pragma unroll 8
    for (int j = 0; j < CW; j++) {
        ulonglong2 xy = t_xy[j], zw = t_zw[j];
        u64 sq = fma2(X, xy.x, fma2(Y, xy.y, fma2(Z, zw.x, add2(P, zw.y))));
        float s0, s1;
        upk2(s0, s1, sq);
        a0 += fex2(fsqrt_a(fmaxf(s0, FEPS)) * c1);
        a1 += fex2(fsqrt_a(fmaxf(s1, FEPS)) * c1);
    }
    g_colpart[b][nc][m0] = a0;
    g_colpart[b][nc][m1] = a1;
}

// ---------------- K4: main pass partials (e on f32 MUFU, h on f16x2 MUFU) ----------------
// grid (4 ntile, 32 mchunk, 8 b), 256 threads; thread owns n0, n0+256.
__global__ void k_main_part(const float* __restrict__ src, const float* __restrict__ tgt,
                            const int* __restrict__ iter) {
    int b = blockIdx.z, nt = blockIdx.x, mc = blockIdx.y, tid = threadIdx.x;
    int n0 = nt * 512 + tid, n1 = n0 + 256;
    int mb = mc * CW;
    const float* S = src + b * 3 * NN;
    const float* T = tgt + b * 3 * MM;
    __shared__ ulonglong2 t_xy[CW];
    __shared__ ulonglong2 t_zw[CW];
    __shared__ u64 t_ic[CW];
    if (tid < CW) {
        int m = mb + tid;
        float x = T[m], y = T[MM + m], z = T[2 * MM + m];
        float w = x * x + y * y + z * z;
        t_xy[tid] = make_ulonglong2(pk2(x, x), pk2(y, y));
        t_zw[tid] = make_ulonglong2(pk2(z, z), pk2(w, w));
        float cs = 0.0f;
#pragma unroll
        for (int nc = 0; nc < NC; nc++) cs += g_colpart[b][nc][m];
        float ic = frcp_a(cs);
        t_ic[tid] = pk2(ic, ic);
    }
    float x0 = S[n0], y0 = S[NN + n0], z0 = S[2 * NN + n0];
    float x1 = S[n1], y1 = S[NN + n1], z1 = S[2 * NN + n1];
    u64 X = pk2(-2.f * x0, -2.f * x1), Y = pk2(-2.f * y0, -2.f * y1), Z = pk2(-2.f * z0, -2.f * z1);
    u64 P = pk2(x0 * x0 + y0 * y0 + z0 * z0, x1 * x1 + y1 * y1 + z1 * z1);
    float c1 = -g_invt[b] * L2E;
    float invT = fex2((float)(*iter - 1));      // 1/T = 2^(iter-1)
    float ch = 2.0f * c1 - invT * L2E;          // e^2 * f = exp2(ch * d)
    __syncthreads();
    u64 R = 0, Sv = 0, G = 0, C0a = 0, C1a = 0, C2a = 0;
#pragma unroll 4
    for (int j = 0; j < CW; j++) {
        ulonglong2 xy = t_xy[j], zw = t_zw[j];
        u64 ic = t_ic[j];
        u64 sq = fma2(X, xy.x, fma2(Y, xy.y, fma2(Z, zw.x, add2(P, zw.y))));
        float q0, q1;
        upk2(q0, q1, sq);
        float d0 = fsqrt_a(fmaxf(q0, FEPS));
        float d1 = fsqrt_a(fmaxf(q1, FEPS));
        float e0 = fex2(d0 * c1), e1 = fex2(d1 * c1);    // softmax numerator (f32 MUFU)
        u64 h2 = ex2_f16pair(d0 * ch, d1 * ch);          // e^2*exp(-d/T), one f16x2 MUFU
        u64 e2 = pk2(e0, e1);
        u64 w = mul2(mul2(e2, e2), ic);
        R = add2(R, e2);
        Sv = add2(Sv, w);
        G = fma2(h2, ic, G);
        C0a = fma2(w, xy.x, C0a);
        C1a = fma2(w, xy.y, C1a);
        C2a = fma2(w, zw.x, C2a);
    }
    float v0, v1;
    upk2(v0, v1, R);   g_part6[b][mc][0][n0] = v0; g_part6[b][mc][0][n1] = v1;
    upk2(v0, v1, Sv);  g_part6[b][mc][1][n0] = v0; g_part6[b][mc][1][n1] = v1;
    upk2(v0, v1, G);   g_part6[b][mc][2][n0] = v0; g_part6[b][mc][2][n1] = v1;
    upk2(v0, v1, C0a); g_part6[b][mc][3][n0] = v0; g_part6[b][mc][3][n1] = v1;
    upk2(v0, v1, C1a); g_part6[b][mc][4][n0] = v0; g_part6[b][mc][4][n1] = v1;
    upk2(v0, v1, C2a); g_part6[b][mc][5][n0] = v0; g_part6[b][mc][5][n1] = v1;
}

// ---------------- 3x3 Procrustes SVD (double, one thread) ----------------
__device__ void svd3_kabsch(const double H[3][3], double R[3][3]) {
    double A[3][3];
    for (int i = 0; i < 3; i++)
        for (int j = 0; j < 3; j++) {
            double s = 0;
            for (int k = 0; k < 3; k++) s += H[k][i] * H[k][j];
            A[i][j] = s;
        }
    double V[3][3] = {{1,0,0},{0,1,0},{0,0,1}};
    const int PQ[3][2] = {{0,1},{0,2},{1,2}};
    for (int sweep = 0; sweep < 30; sweep++) {
        double off = fabs(A[0][1]) + fabs(A[0][2]) + fabs(A[1][2]);
        if (off < 1e-30) break;
        for (int r = 0; r < 3; r++) {
            int p = PQ[r][0], q = PQ[r][1];
            double apq = A[p][q];
            if (fabs(apq) < 1e-300) continue;
            double theta = (A[q][q] - A[p][p]) / (2.0 * apq);
            double t = ((theta >= 0.0) ? 1.0 : -1.0) / (fabs(theta) + sqrt(1.0 + theta * theta));
            double c = 1.0 / sqrt(1.0 + t * t), s = t * c;
            for (int k = 0; k < 3; k++) {
                double akp = A[k][p], akq = A[k][q];
                A[k][p] = c * akp - s * akq;
                A[k][q] = s * akp + c * akq;
            }
            for (int k = 0; k < 3; k++) {
                double apk = A[p][k], aqk = A[q][k];
                A[p][k] = c * apk - s * aqk;
                A[q][k] = s * apk + c * aqk;
            }
            for (int k = 0; k < 3; k++) {
                double vkp = V[k][p], vkq = V[k][q];
                V[k][p] = c * vkp - s * vkq;
                V[k][q] = s * vkp + c * vkq;
            }
        }
    }
    int idx[3] = {0, 1, 2};
    double lam[3] = {A[0][0], A[1][1], A[2][2]};
    for (int i = 0; i < 2; i++)
        for (int j = i + 1; j < 3; j++)
            if (lam[idx[j]] > lam[idx[i]]) { int t = idx[i]; idx[i] = idx[j]; idx[j] = t; }
    double U[3][3], Vs[3][3];
    for (int i = 0; i < 3; i++) {
        int id = idx[i];
        double v0 = V[0][id], v1 = V[1][id], v2 = V[2][id];
        double u0 = H[0][0]*v0 + H[0][1]*v1 + H[0][2]*v2;
        double u1 = H[1][0]*v0 + H[1][1]*v1 + H[1][2]*v2;
        double u2 = H[2][0]*v0 + H[2][1]*v1 + H[2][2]*v2;
        double sig = sqrt(u0*u0 + u1*u1 + u2*u2);
        sig = (sig > 1e-300) ? sig : 1e-300;
        U[0][i] = u0 / sig; U[1][i] = u1 / sig; U[2][i] = u2 / sig;
        Vs[0][i] = v0; Vs[1][i] = v1; Vs[2][i] = v2;
    }
    double detH = H[0][0]*(H[1][1]*H[2][2] - H[1][2]*H[2][1])
                - H[0][1]*(H[1][0]*H[2][2] - H[1][2]*H[2][0])
                + H[0][2]*(H[1][0]*H[2][1] - H[1][1]*H[2][0]);
    double flip = (detH < 0.0) ? -1.0 : 1.0;
    Vs[0][2] *= flip; Vs[1][2] *= flip; Vs[2][2] *= flip;
    for (int r = 0; r < 3; r++)
        for (int c = 0; c < 3; c++)
            R[r][c] = Vs[r][0]*U[c][0] + Vs[r][1]*U[c][1] + Vs[r][2]*U[c][2];
}

// ---------------- K5: finalize per-n + H partials + (last block per batch) SVD ----------------
// grid (32 ntile, 8 b), 64 threads (2 warps); thread owns one n.
// out: [0,72) R, [72,96) t, [96,...) src_corr
__global__ void k_finalize(const float* __restrict__ src, float* __restrict__ out) {
    int nt = blockIdx.x, b = blockIdx.y, tid = threadIdx.x;
    int lane = tid & 31, wrp = tid >> 5;
    int n = nt * 64 + tid;
    const float* S = src + b * 3 * NN;
    float* corr = out + 96 + b * 3 * NN;
    float Rn = 0.f, S2 = 0.f, G = 0.f, c0 = 0.f, c1 = 0.f, c2 = 0.f;
#pragma unroll 8
    for (int mc = 0; mc < NC; mc++) {
        Rn += g_part6[b][mc][0][n];
        S2 += g_part6[b][mc][1][n];
        G  += g_part6[b][mc][2][n];
        c0 += g_part6[b][mc][3][n];
        c1 += g_part6[b][mc][4][n];
        c2 += g_part6[b][mc][5][n];
    }
    float g = G / Rn;
    float invden = 1.0f / (S2 + FEPS * Rn);
    float cx = c0 * invden, cy = c1 * invden, cz = c2 * invden;
    corr[n]          = cx;
    corr[NN + n]     = cy;
    corr[2 * NN + n] = cz;
    float sx = S[n], sy = S[NN + n], sz = S[2 * NN + n];
    float acc[16];
    acc[0] = g;
    acc[1] = g * sx;  acc[2] = g * sy;  acc[3] = g * sz;
    acc[4] = g * cx;  acc[5] = g * cy;  acc[6] = g * cz;
    acc[7]  = g * sx * cx; acc[8]  = g * sx * cy; acc[9]  = g * sx * cz;
    acc[10] = g * sy * cx; acc[11] = g * sy * cy; acc[12] = g * sy * cz;
    acc[13] = g * sz * cx; acc[14] = g * sz * cy; acc[15] = g * sz * cz;
    // warp-shuffle reduction of 16 values
#pragma unroll
    for (int k = 0; k < 16; k++) {
#pragma unroll
        for (int off = 16; off > 0; off >>= 1)
            acc[k] += __shfl_down_sync(0xFFFFFFFFu, acc[k], off);
    }
    __shared__ float red[2][16];
    if (lane == 0) {
#pragma unroll
        for (int k = 0; k < 16; k++) red[wrp][k] = acc[k];
    }
    __syncthreads();
    if (tid < 16) g_hpart[b][nt][tid] = red[0][tid] + red[1][tid];

    // ---- last block per batch (32 blocks): sum tiles + SVD ----
    __shared__ unsigned s_last;
    __shared__ float tot_sh[16];
    __syncthreads();
    if (tid == 0) {
        __threadfence();
        unsigned old = atomicAdd(&g_cnt[b], 1u);
        s_last = ((old & 31u) == 31u) ? 1u : 0u;
    }
    __syncthreads();
    if (!s_last) return;
    __threadfence();
    if (tid < 16) {
        float s = 0.f;
#pragma unroll
        for (int t = 0; t < 32; t++) s += g_hpart[b][t][tid];
        tot_sh[tid] = s;
    }
    __syncthreads();
    if (tid != 0) return;
    float tot[16];
#pragma unroll
    for (int k = 0; k < 16; k++) tot[k] = tot_sh[k];
    double g1 = tot[0];
    double Ss[3] = {tot[1], tot[2], tot[3]};
    double Sc[3] = {tot[4], tot[5], tot[6]};
    double Mm[3][3] = {{tot[7], tot[8], tot[9]},
                       {tot[10], tot[11], tot[12]},
                       {tot[13], tot[14], tot[15]}};
    double gsum = g1 + 1e-12;
    double sm[3], cm[3];
    for (int d = 0; d < 3; d++) { sm[d] = Ss[d] / gsum; cm[d] = Sc[d] / gsum; }
    double H[3][3];
    for (int r = 0; r < 3; r++)
        for (int c = 0; c < 3; c++)
            H[r][c] = Mm[r][c] - sm[r] * Sc[c] - cm[c] * Ss[r] + sm[r] * cm[c] * g1;
    H[0][0] += 1e-12; H[1][1] += 2e-12; H[2][2] += 3e-12;
    double R3[3][3];
    svd3_kabsch(H, R3);
    for (int r = 0; r < 3; r++)
        for (int c = 0; c < 3; c++)
            out[b * 9 + r * 3 + c] = (float)R3[r][c];
    for (int d = 0; d < 3; d++)
        out[72 + b * 3 + d] =
            (float)(-(R3[d][0] * sm[0] + R3[d][1] * sm[1] + R3[d][2] * sm[2]) + cm[d]);
}

// ---------------- launch ----------------
extern "C" void kernel_launch(void* const* d_in, const int* in_sizes, int n_in,
                              void* d_out, int out_size) {
    const float* src = (const float*)d_in[0];
    const float* tgt = (const float*)d_in[1];
    const int* iter = (const int*)d_in[2];
    float* out = (float*)d_out;

    k_alpha_part<<<dim3(4, NC, 8), 256>>>(src);
    k_alpha_comb<<<8, 256>>>();
    k_colsum_part<<<dim3(4, NC, 8), 256>>>(src, tgt);
    k_main_part<<<dim3(4, NC, 8), 256>>>(src, tgt, iter);
    k_finalize<<<dim3(32, 8), 64>>>(src, out);
}

// round 16
// speedup vs baseline: 1.0667x; 1.0144x over previous
#include <cuda_runtime.h>
#include <math.h>

typedef unsigned long long u64;

#define BB 8
#define NN 2048
#define MM 2048
#define NC 32        // chunks along reduced dim
#define CW 64        // chunk width
#define FEPS 1e-12f
#define L2E 1.4426950408889634f

// ---------------- scratch (device globals; no allocs allowed) ----------------
__device__ float g_invt[BB];
__device__ float g_minsq[BB][NC][NN];
__device__ float g_colpart[BB][NC][MM];
__device__ float g_part6[BB][NC][6][NN];
__device__ float g_hpart[BB][32][16];
__device__ unsigned g_cnt[BB];    // finalize last-block counter (mod-32 parity)

// ---------------- f32x2 + MUFU helpers ----------------
__device__ __forceinline__ u64 pk2(float lo, float hi) {
    u64 r; asm("mov.b64 %0,{%1,%2};" : "=l"(r) : "f"(lo), "f"(hi)); return r;
}
__device__ __forceinline__ void upk2(float& lo, float& hi, u64 v) {
    asm("mov.b64 {%0,%1},%2;" : "=f"(lo), "=f"(hi) : "l"(v));
}
__device__ __forceinline__ u64 fma2(u64 a, u64 b, u64 c) {
    u64 d; asm("fma.rn.f32x2 %0,%1,%2,%3;" : "=l"(d) : "l"(a), "l"(b), "l"(c)); return d;
}
__device__ __forceinline__ u64 add2(u64 a, u64 b) {
    u64 d; asm("add.rn.f32x2 %0,%1,%2;" : "=l"(d) : "l"(a), "l"(b)); return d;
}
__device__ __forceinline__ u64 mul2(u64 a, u64 b) {
    u64 d; asm("mul.rn.f32x2 %0,%1,%2;" : "=l"(d) : "l"(a), "l"(b)); return d;
}
__device__ __forceinline__ float fsqrt_a(float x) {
    float r; asm("sqrt.approx.f32 %0,%1;" : "=f"(r) : "f"(x)); return r;
}
__device__ __forceinline__ float fex2(float x) {
    float r; asm("ex2.approx.f32 %0,%1;" : "=f"(r) : "f"(x)); return r;
}
__device__ __forceinline__ float frcp_a(float x) {
    float r; asm("rcp.approx.f32 %0,%1;" : "=f"(r) : "f"(x)); return r;
}

// One MUFU op for TWO exponentials at f16 precision (~5e-4 rel).
// Returns packed f32x2 (lo = exp2(a0), hi = exp2(a1)).
__device__ __forceinline__ u64 ex2_f16pair(float a0, float a1) {
    unsigned p;
    asm("{\n\t"
        ".reg .f16x2 t;\n\t"
        "cvt.rn.f16x2.f32 t, %1, %2;\n\t"   // hi = a1, lo = a0
        "ex2.approx.f16x2 t, t;\n\t"
        "mov.b32 %0, t;\n\t"
        "}" : "=r"(p) : "f"(a1), "f"(a0));
    float lo, hi;
    asm("{\n\t"
        ".reg .f16 l, h;\n\t"
        "mov.b32 {l, h}, %2;\n\t"
        "cvt.f32.f16 %0, l;\n\t"
        "cvt.f32.f16 %1, h;\n\t"
        "}" : "=f"(lo), "=f"(hi) : "r"(p));
    return pk2(lo, hi);
}

// ---------------- K1: alpha partial min (packed pair, diag-split) ----------------
// grid (4 ntile, 32 mchunk, 8 b), 256 threads; thread owns n0 = nt*512+tid, n1 = n0+256.
__global__ void k_alpha_part(const float* __restrict__ src) {
    int b = blockIdx.z, nt = blockIdx.x, mc = blockIdx.y, tid = threadIdx.x;
    int n0 = nt * 512 + tid, n1 = n0 + 256;
    int mb = mc * CW;
    const float* S = src + b * 3 * NN;
    __shared__ ulonglong2 t_xy[CW];
    __shared__ ulonglong2 t_zw[CW];
    if (tid < CW) {
        int m = mb + tid;
        float x = S[m], y = S[NN + m], z = S[2 * NN + m];
        float w = x * x + y * y + z * z;
        t_xy[tid] = make_ulonglong2(pk2(x, x), pk2(y, y));
        t_zw[tid] = make_ulonglong2(pk2(z, z), pk2(w, w));
    }
    float x0 = S[n0], y0 = S[NN + n0], z0 = S[2 * NN + n0];
    float x1 = S[n1], y1 = S[NN + n1], z1 = S[2 * NN + n1];
    u64 X = pk2(-2.f * x0, -2.f * x1), Y = pk2(-2.f * y0, -2.f * y1), Z = pk2(-2.f * z0, -2.f * z1);
    u64 P = pk2(x0 * x0 + y0 * y0 + z0 * z0, x1 * x1 + y1 * y1 + z1 * z1);
    int jd0 = n0 - mb, jd1 = n1 - mb;   // diagonal hit only if in [0,CW)
    __syncthreads();
    float mn0 = 1e30f, mn1 = 1e30f;
    bool has_diag = ((unsigned)jd0 < CW) || ((unsigned)jd1 < CW);
    if (has_diag) {
#pragma unroll 8
        for (int j = 0; j < CW; j++) {
            ulonglong2 xy = t_xy[j], zw = t_zw[j];
            u64 sq = fma2(X, xy.x, fma2(Y, xy.y, fma2(Z, zw.x, add2(P, zw.y))));
            float s0, s1;
            upk2(s0, s1, sq);
            if (j == jd0) s0 = 1e30f;
            if (j == jd1) s1 = 1e30f;
            mn0 = fminf(mn0, s0);
            mn1 = fminf(mn1, s1);
        }
    } else {
#pragma unroll 8
        for (int j = 0; j < CW; j++) {
            ulonglong2 xy = t_xy[j], zw = t_zw[j];
            u64 sq = fma2(X, xy.x, fma2(Y, xy.y, fma2(Z, zw.x, add2(P, zw.y))));
            float s0, s1;
            upk2(s0, s1, sq);
            mn0 = fminf(mn0, s0);
            mn1 = fminf(mn1, s1);
        }
    }
    g_minsq[b][mc][n0] = mn0;
    g_minsq[b][mc][n1] = mn1;
}

// ---------------- K2: combine alpha -> invt ----------------
__global__ void k_alpha_comb() {
    int b = blockIdx.x, tid = threadIdx.x;
    __shared__ float red[256];
    float s = 0.0f;
    for (int n = tid; n < NN; n += 256) {
        float mn = 1e30f;
#pragma unroll
        for (int mc = 0; mc < NC; mc++) mn = fminf(mn, g_minsq[b][mc][n]);
        s += fsqrt_a(fmaxf(mn, FEPS));
    }
    red[tid] = s; __syncthreads();
    for (int st = 128; st > 0; st >>= 1) {
        if (tid < st) red[tid] += red[tid + st];
        __syncthreads();
    }
    if (tid == 0) {
        float alpha = red[0] * (1.0f / (float)NN);
        g_invt[b] = 1.0f / (4.0f * alpha);
    }
}

// ---------------- K3: column softmax denominators (f16x2 exp pair) ----------------
// grid (4 mtile, 32 nchunk, 8 b), 256 threads; thread owns m0, m0+256.
__global__ void k_colsum_part(const float* __restrict__ src, const float* __restrict__ tgt) {
    int b = blockIdx.z, mt = blockIdx.x, nc = blockIdx.y, tid = threadIdx.x;
    int m0 = mt * 512 + tid, m1 = m0 + 256;
    int nb = nc * CW;
    const float* S = src + b * 3 * NN;
    const float* T = tgt + b * 3 * MM;
    __shared__ ulonglong2 t_xy[CW];
    __shared__ ulonglong2 t_zw[CW];
    if (tid < CW) {
        int m = nb + tid;
        float x = S[m], y = S[NN + m], z = S[2 * NN + m];
        float w = x * x + y * y + z * z;
        t_xy[tid] = make_ulonglong2(pk2(x, x), pk2(y, y));
        t_zw[tid] = make_ulonglong2(pk2(z, z), pk2(w, w));
    }
    float x0 = T[m0], y0 = T[MM + m0], z0 = T[2 * MM + m0];
    float x1 = T[m1], y1 = T[MM + m1], z1 = T[2 * MM + m1];
    u64 X = pk2(-2.f * x0, -2.f * x1), Y = pk2(-2.f * y0, -2.f * y1), Z = pk2(-2.f * z0, -2.f * z1);
    u64 P = pk2(x0 * x0 + y0 * y0 + z0 * z0, x1 * x1 + y1 * y1 + z1 * z1);
    float c1 = -g_invt[b] * L2E;
    __syncthreads();
    u64 A = 0;
#pragma unroll 8
    for (int j = 0; j < CW; j++) {
        ulonglong2 xy = t_xy[j], zw = t_zw[j];
        u64 sq = fma2(X, xy.x, fma2(Y, xy.y, fma2(Z, zw.x, add2(P, zw.y))));
        float s0, s1;
        upk2(s0, s1, sq);
        float d0 = fsqrt_a(fmaxf(s0, FEPS));
        float d1 = fsqrt_a(fmaxf(s1, FEPS));
        A = add2(A, ex2_f16pair(d0 * c1, d1 * c1));   // one MUFU for both exps
    }
    float a0, a1;
    upk2(a0, a1, A);
    g_colpart[b][nc][m0] = a0;
    g_colpart[b][nc][m1] = a1;
}

// ---------------- K4: main pass partials (e on f32 MUFU, h on f16x2 MUFU) ----------------
// grid (4 ntile, 32 mchunk, 8 b), 256 threads; thread owns n0, n0+256.
__global__ void k_main_part(const float* __restrict__ src, const float* __restrict__ tgt,
                            const int* __restrict__ iter) {
    int b = blockIdx.z, nt = blockIdx.x, mc = blockIdx.y, tid = threadIdx.x;
    int n0 = nt * 512 + tid, n1 = n0 + 256;
    int mb = mc * CW;
    const float* S = src + b * 3 * NN;
    const float* T = tgt + b * 3 * MM;
    __shared__ ulonglong2 t_xy[CW];
    __shared__ ulonglong2 t_zw[CW];
    __shared__ u64 t_ic[CW];
    if (tid < CW) {
        int m = mb + tid;
        float x = T[m], y = T[MM + m], z = T[2 * MM + m];
        float w = x * x + y * y + z * z;
        t_xy[tid] = make_ulonglong2(pk2(x, x), pk2(y, y));
        t_zw[tid] = make_ulonglong2(pk2(z, z), pk2(w, w));
        float cs = 0.0f;
#pragma unroll
        for (int nc = 0; nc < NC; nc++) cs += g_colpart[b][nc][m];
        float ic = frcp_a(cs);
        t_ic[tid] = pk2(ic, ic);
    }
    float x0 = S[n0], y0 = S[NN + n0], z0 = S[2 * NN + n0];
    float x1 = S[n1], y1 = S[NN + n1], z1 = S[2 * NN + n1];
    u64 X = pk2(-2.f * x0, -2.f * x1), Y = pk2(-2.f * y0, -2.f * y1), Z = pk2(-2.f * z0, -2.f * z1);
    u64 P = pk2(x0 * x0 + y0 * y0 + z0 * z0, x1 * x1 + y1 * y1 + z1 * z1);
    float c1 = -g_invt[b] * L2E;
    float invT = fex2((float)(*iter - 1));      // 1/T = 2^(iter-1)
    float ch = 2.0f * c1 - invT * L2E;          // e^2 * f = exp2(ch * d)
    __syncthreads();
    u64 R = 0, Sv = 0, G = 0, C0a = 0, C1a = 0, C2a = 0;
#pragma unroll 4
    for (int j = 0; j < CW; j++) {
        ulonglong2 xy = t_xy[j], zw = t_zw[j];
        u64 ic = t_ic[j];
        u64 sq = fma2(X, xy.x, fma2(Y, xy.y, fma2(Z, zw.x, add2(P, zw.y))));
        float q0, q1;
        upk2(q0, q1, sq);
        float d0 = fsqrt_a(fmaxf(q0, FEPS));
        float d1 = fsqrt_a(fmaxf(q1, FEPS));
        float e0 = fex2(d0 * c1), e1 = fex2(d1 * c1);    // softmax numerator (f32 MUFU)
        u64 h2 = ex2_f16pair(d0 * ch, d1 * ch);          // e^2*exp(-d/T), one f16x2 MUFU
        u64 e2 = pk2(e0, e1);
        u64 w = mul2(mul2(e2, e2), ic);
        R = add2(R, e2);
        Sv = add2(Sv, w);
        G = fma2(h2, ic, G);
        C0a = fma2(w, xy.x, C0a);
        C1a = fma2(w, xy.y, C1a);
        C2a = fma2(w, zw.x, C2a);
    }
    float v0, v1;
    upk2(v0, v1, R);   g_part6[b][mc][0][n0] = v0; g_part6[b][mc][0][n1] = v1;
    upk2(v0, v1, Sv);  g_part6[b][mc][1][n0] = v0; g_part6[b][mc][1][n1] = v1;
    upk2(v0, v1, G);   g_part6[b][mc][2][n0] = v0; g_part6[b][mc][2][n1] = v1;
    upk2(v0, v1, C0a); g_part6[b][mc][3][n0] = v0; g_part6[b][mc][3][n1] = v1;
    upk2(v0, v1, C1a); g_part6[b][mc][4][n0] = v0; g_part6[b][mc][4][n1] = v1;
    upk2(v0, v1, C2a); g_part6[b][mc][5][n0] = v0; g_part6[b][mc][5][n1] = v1;
}

// ---------------- 3x3 Procrustes SVD (double, one thread) ----------------
__device__ void svd3_kabsch(const double H[3][3], double R[3][3]) {
    double A[3][3];
    for (int i = 0; i < 3; i++)
        for (int j = 0; j < 3; j++) {
            double s = 0;
            for (int k = 0; k < 3; k++) s += H[k][i] * H[k][j];
            A[i][j] = s;
        }
    double V[3][3] = {{1,0,0},{0,1,0},{0,0,1}};
    const int PQ[3][2] = {{0,1},{0,2},{1,2}};
    for (int sweep = 0; sweep < 30; sweep++) {
        double off = fabs(A[0][1]) + fabs(A[0][2]) + fabs(A[1][2]);
        if (off < 1e-30) break;
        for (int r = 0; r < 3; r++) {
            int p = PQ[r][0], q = PQ[r][1];
            double apq = A[p][q];
            if (fabs(apq) < 1e-300) continue;
            double theta = (A[q][q] - A[p][p]) / (2.0 * apq);
            double t = ((theta >= 0.0) ? 1.0 : -1.0) / (fabs(theta) + sqrt(1.0 + theta * theta));
            double c = 1.0 / sqrt(1.0 + t * t), s = t * c;
            for (int k = 0; k < 3; k++) {
                double akp = A[k][p], akq = A[k][q];
                A[k][p] = c * akp - s * akq;
                A[k][q] = s * akp + c * akq;
            }
            for (int k = 0; k < 3; k++) {
                double apk = A[p][k], aqk = A[q][k];
                A[p][k] = c * apk - s * aqk;
                A[q][k] = s * apk + c * aqk;
            }
            for (int k = 0; k < 3; k++) {
                double vkp = V[k][p], vkq = V[k][q];
                V[k][p] = c * vkp - s * vkq;
                V[k][q] = s * vkp + c * vkq;
            }
        }
    }
    int idx[3] = {0, 1, 2};
    double lam[3] = {A[0][0], A[1][1], A[2][2]};
    for (int i = 0; i < 2; i++)
        for (int j = i + 1; j < 3; j++)
            if (lam[idx[j]] > lam[idx[i]]) { int t = idx[i]; idx[i] = idx[j]; idx[j] = t; }
    double U[3][3], Vs[3][3];
    for (int i = 0; i < 3; i++) {
        int id = idx[i];
        double v0 = V[0][id], v1 = V[1][id], v2 = V[2][id];
        double u0 = H[0][0]*v0 + H[0][1]*v1 + H[0][2]*v2;
        double u1 = H[1][0]*v0 + H[1][1]*v1 + H[1][2]*v2;
        double u2 = H[2][0]*v0 + H[2][1]*v1 + H[2][2]*v2;
        double sig = sqrt(u0*u0 + u1*u1 + u2*u2);
        sig = (sig > 1e-300) ? sig : 1e-300;
        U[0][i] = u0 / sig; U[1][i] = u1 / sig; U[2][i] = u2 / sig;
        Vs[0][i] = v0; Vs[1][i] = v1; Vs[2][i] = v2;
    }
    double detH = H[0][0]*(H[1][1]*H[2][2] - H[1][2]*H[2][1])
                - H[0][1]*(H[1][0]*H[2][2] - H[1][2]*H[2][0])
                + H[0][2]*(H[1][0]*H[2][1] - H[1][1]*H[2][0]);
    double flip = (detH < 0.0) ? -1.0 : 1.0;
    Vs[0][2] *= flip; Vs[1][2] *= flip; Vs[2][2] *= flip;
    for (int r = 0; r < 3; r++)
        for (int c = 0; c < 3; c++)
            R[r][c] = Vs[r][0]*U[c][0] + Vs[r][1]*U[c][1] + Vs[r][2]*U[c][2];
}

// ---------------- K5: finalize per-n + H partials + (last block per batch) SVD ----------------
// grid (32 ntile, 8 b), 64 threads (2 warps); thread owns one n.
// out: [0,72) R, [72,96) t, [96,...) src_corr
__global__ void k_finalize(const float* __restrict__ src, float* __restrict__ out) {
    int nt = blockIdx.x, b = blockIdx.y, tid = threadIdx.x;
    int lane = tid & 31, wrp = tid >> 5;
    int n = nt * 64 + tid;
    const float* S = src + b * 3 * NN;
    float* corr = out + 96 + b * 3 * NN;
    float Rn = 0.f, S2 = 0.f, G = 0.f, c0 = 0.f, c1 = 0.f, c2 = 0.f;
#pragma unroll 8
    for (int mc = 0; mc < NC; mc++) {
        Rn += g_part6[b][mc][0][n];
        S2 += g_part6[b][mc][1][n];
        G  += g_part6[b][mc][2][n];
        c0 += g_part6[b][mc][3][n];
        c1 += g_part6[b][mc][4][n];
        c2 += g_part6[b][mc][5][n];
    }
    float g = G / Rn;
    float invden = 1.0f / (S2 + FEPS * Rn);
    float cx = c0 * invden, cy = c1 * invden, cz = c2 * invden;
    corr[n]          = cx;
    corr[NN + n]     = cy;
    corr[2 * NN + n] = cz;
    float sx = S[n], sy = S[NN + n], sz = S[2 * NN + n];
    float acc[16];
    acc[0] = g;
    acc[1] = g * sx;  acc[2] = g * sy;  acc[3] = g * sz;
    acc[4] = g * cx;  acc[5] = g * cy;  acc[6] = g * cz;
    acc[7]  = g * sx * cx; acc[8]  = g * sx * cy; acc[9]  = g * sx * cz;
    acc[10] = g * sy * cx; acc[11] = g * sy * cy; acc[12] = g * sy * cz;
    acc[13] = g * sz * cx; acc[14] = g * sz * cy; acc[15] = g * sz * cz;
#pragma unroll
    for (int k = 0; k < 16; k++) {
#pragma unroll
        for (int off = 16; off > 0; off >>= 1)
            acc[k] += __shfl_down_sync(0xFFFFFFFFu, acc[k], off);
    }
    __shared__ float red[2][16];
    if (lane == 0) {
#pragma unroll
        for (int k = 0; k < 16; k++) red[wrp][k] = acc[k];
    }
    __syncthreads();
    if (tid < 16) g_hpart[b][nt][tid] = red[0][tid] + red[1][tid];

    // ---- last block per batch (32 blocks): sum tiles + SVD ----
    __shared__ unsigned s_last;
    __shared__ float tot_sh[16];
    __syncthreads();
    if (tid == 0) {
        __threadfence();
        unsigned old = atomicAdd(&g_cnt[b], 1u);
        s_last = ((old & 31u) == 31u) ? 1u : 0u;
    }
    __syncthreads();
    if (!s_last) return;
    __threadfence();
    if (tid < 16) {
        float s = 0.f;
#pragma unroll
        for (int t = 0; t < 32; t++) s += g_hpart[b][t][tid];
        tot_sh[tid] = s;
    }
    __syncthreads();
    if (tid != 0) return;
    float tot[16];
#pragma unroll
    for (int k = 0; k < 16; k++) tot[k] = tot_sh[k];
    double g1 = tot[0];
    double Ss[3] = {tot[1], tot[2], tot[3]};
    double Sc[3] = {tot[4], tot[5], tot[6]};
    double Mm[3][3] = {{tot[7], tot[8], tot[9]},
                       {tot[10], tot[11], tot[12]},
                       {tot[13], tot[14], tot[15]}};
    double gsum = g1 + 1e-12;
    double sm[3], cm[3];
    for (int d = 0; d < 3; d++) { sm[d] = Ss[d] / gsum; cm[d] = Sc[d] / gsum; }
    double H[3][3];
    for (int r = 0; r < 3; r++)
        for (int c = 0; c < 3; c++)
            H[r][c] = Mm[r][c] - sm[r] * Sc[c] - cm[c] * Ss[r] + sm[r] * cm[c] * g1;
    H[0][0] += 1e-12; H[1][1] += 2e-12; H[2][2] += 3e-12;
    double R3[3][3];
    svd3_kabsch(H, R3);
    for (int r = 0; r < 3; r++)
        for (int c = 0; c < 3; c++)
            out[b * 9 + r * 3 + c] = (float)R3[r][c];
    for (int d = 0; d < 3; d++)
        out[72 + b * 3 + d] =
            (float)(-(R3[d][0] * sm[0] + R3[d][1] * sm[1] + R3[d][2] * sm[2]) + cm[d]);
}

// ---------------- launch ----------------
extern "C" void kernel_launch(void* const* d_in, const int* in_sizes, int n_in,
                              void* d_out, int out_size) {
    const float* src = (const float*)d_in[0];
    const float* tgt = (const float*)d_in[1];
    const int* iter = (const int*)d_in[2];
    float* out = (float*)d_out;

    k_alpha_part<<<dim3(4, NC, 8), 256>>>(src);
    k_alpha_comb<<<8, 256>>>();
    k_colsum_part<<<dim3(4, NC, 8), 256>>>(src, tgt);
    k_main_part<<<dim3(4, NC, 8), 256>>>(src, tgt, iter);
    k_finalize<<<dim3(32, 8), 64>>>(src, out);
}

// round 17
// speedup vs baseline: 1.1029x; 1.0339x over previous
#include <cuda_runtime.h>
#include <math.h>

typedef unsigned long long u64;

#define BB 8
#define NN 2048
#define MM 2048
#define NC 32        // chunks along reduced dim
#define CW 64        // chunk width
#define FEPS 1e-12f
#define L2E 1.4426950408889634f

// ---------------- scratch (device globals; no allocs allowed) ----------------
__device__ float g_invt[BB];
__device__ float g_minsq[BB][NC][NN];
__device__ float g_colpart[BB][NC][MM];
__device__ float g_part6[BB][NC][6][NN];
__device__ float g_hpart[BB][32][16];
__device__ unsigned g_cnt[BB];    // finalize last-block counter (mod-32 parity)

// ---------------- f32x2 + MUFU helpers ----------------
__device__ __forceinline__ u64 pk2(float lo, float hi) {
    u64 r; asm("mov.b64 %0,{%1,%2};" : "=l"(r) : "f"(lo), "f"(hi)); return r;
}
__device__ __forceinline__ void upk2(float& lo, float& hi, u64 v) {
    asm("mov.b64 {%0,%1},%2;" : "=f"(lo), "=f"(hi) : "l"(v));
}
__device__ __forceinline__ u64 fma2(u64 a, u64 b, u64 c) {
    u64 d; asm("fma.rn.f32x2 %0,%1,%2,%3;" : "=l"(d) : "l"(a), "l"(b), "l"(c)); return d;
}
__device__ __forceinline__ u64 add2(u64 a, u64 b) {
    u64 d; asm("add.rn.f32x2 %0,%1,%2;" : "=l"(d) : "l"(a), "l"(b)); return d;
}
__device__ __forceinline__ u64 mul2(u64 a, u64 b) {
    u64 d; asm("mul.rn.f32x2 %0,%1,%2;" : "=l"(d) : "l"(a), "l"(b)); return d;
}
__device__ __forceinline__ float fsqrt_a(float x) {
    float r; asm("sqrt.approx.f32 %0,%1;" : "=f"(r) : "f"(x)); return r;
}
__device__ __forceinline__ float fex2(float x) {
    float r; asm("ex2.approx.f32 %0,%1;" : "=f"(r) : "f"(x)); return r;
}
__device__ __forceinline__ float frcp_a(float x) {
    float r; asm("rcp.approx.f32 %0,%1;" : "=f"(r) : "f"(x)); return r;
}

// One MUFU op for TWO exponentials at f16 precision (~5e-4 rel).
__device__ __forceinline__ u64 ex2_f16pair(float a0, float a1) {
    unsigned p;
    asm("{\n\t"
        ".reg .f16x2 t;\n\t"
        "cvt.rn.f16x2.f32 t, %1, %2;\n\t"   // hi = a1, lo = a0
        "ex2.approx.f16x2 t, t;\n\t"
        "mov.b32 %0, t;\n\t"
        "}" : "=r"(p) : "f"(a1), "f"(a0));
    float lo, hi;
    asm("{\n\t"
        ".reg .f16 l, h;\n\t"
        "mov.b32 {l, h}, %2;\n\t"
        "cvt.f32.f16 %0, l;\n\t"
        "cvt.f32.f16 %1, h;\n\t"
        "}" : "=f"(lo), "=f"(hi) : "r"(p));
    return pk2(lo, hi);
}

// ---------------- K1: alpha partial min (packed pair, diag-split) ----------------
// grid (4 ntile, 32 mchunk, 8 b), 256 threads; thread owns n0 = nt*512+tid, n1 = n0+256.
__global__ void k_alpha_part(const float* __restrict__ src) {
    int b = blockIdx.z, nt = blockIdx.x, mc = blockIdx.y, tid = threadIdx.x;
    int n0 = nt * 512 + tid, n1 = n0 + 256;
    int mb = mc * CW;
    const float* S = src + b * 3 * NN;
    __shared__ ulonglong2 t_xy[CW];
    __shared__ ulonglong2 t_zw[CW];
    if (tid < CW) {
        int m = mb + tid;
        float x = S[m], y = S[NN + m], z = S[2 * NN + m];
        float w = x * x + y * y + z * z;
        t_xy[tid] = make_ulonglong2(pk2(x, x), pk2(y, y));
        t_zw[tid] = make_ulonglong2(pk2(z, z), pk2(w, w));
    }
    float x0 = S[n0], y0 = S[NN + n0], z0 = S[2 * NN + n0];
    float x1 = S[n1], y1 = S[NN + n1], z1 = S[2 * NN + n1];
    u64 X = pk2(-2.f * x0, -2.f * x1), Y = pk2(-2.f * y0, -2.f * y1), Z = pk2(-2.f * z0, -2.f * z1);
    u64 P = pk2(x0 * x0 + y0 * y0 + z0 * z0, x1 * x1 + y1 * y1 + z1 * z1);
    int jd0 = n0 - mb, jd1 = n1 - mb;   // diagonal hit only if in [0,CW)
    __syncthreads();
    float mn0 = 1e30f, mn1 = 1e30f;
    bool has_diag = ((unsigned)jd0 < CW) || ((unsigned)jd1 < CW);
    if (has_diag) {
#pragma unroll 8
        for (int j = 0; j < CW; j++) {
            ulonglong2 xy = t_xy[j], zw = t_zw[j];
            u64 sq = fma2(X, xy.x, fma2(Y, xy.y, fma2(Z, zw.x, add2(P, zw.y))));
            float s0, s1;
            upk2(s0, s1, sq);
            if (j == jd0) s0 = 1e30f;
            if (j == jd1) s1 = 1e30f;
            mn0 = fminf(mn0, s0);
            mn1 = fminf(mn1, s1);
        }
    } else {
#pragma unroll 8
        for (int j = 0; j < CW; j++) {
            ulonglong2 xy = t_xy[j], zw = t_zw[j];
            u64 sq = fma2(X, xy.x, fma2(Y, xy.y, fma2(Z, zw.x, add2(P, zw.y))));
            float s0, s1;
            upk2(s0, s1, sq);
            mn0 = fminf(mn0, s0);
            mn1 = fminf(mn1, s1);
        }
    }
    g_minsq[b][mc][n0] = mn0;
    g_minsq[b][mc][n1] = mn1;
}

// ---------------- K2: combine alpha -> invt (PDL consumer) ----------------
__global__ void k_alpha_comb() {
    cudaGridDependencySynchronize();
    int b = blockIdx.x, tid = threadIdx.x;
    __shared__ float red[256];
    float s = 0.0f;
    for (int n = tid; n < NN; n += 256) {
        float mn = 1e30f;
#pragma unroll
        for (int mc = 0; mc < NC; mc++) mn = fminf(mn, g_minsq[b][mc][n]);
        s += fsqrt_a(fmaxf(mn, FEPS));
    }
    red[tid] = s; __syncthreads();
    for (int st = 128; st > 0; st >>= 1) {
        if (tid < st) red[tid] += red[tid + st];
        __syncthreads();
    }
    if (tid == 0) {
        float alpha = red[0] * (1.0f / (float)NN);
        g_invt[b] = 1.0f / (4.0f * alpha);
    }
}

// ---------------- K3: column softmax denominators (f16x2 exp pair, PDL) ----------------
// grid (4 mtile, 32 nchunk, 8 b), 256 threads; thread owns m0, m0+256.
__global__ void k_colsum_part(const float* __restrict__ src, const float* __restrict__ tgt) {
    int b = blockIdx.z, mt = blockIdx.x, nc = blockIdx.y, tid = threadIdx.x;
    int m0 = mt * 512 + tid, m1 = m0 + 256;
    int nb = nc * CW;
    const float* S = src + b * 3 * NN;
    const float* T = tgt + b * 3 * MM;
    __shared__ ulonglong2 t_xy[CW];
    __shared__ ulonglong2 t_zw[CW];
    // Pure-input prologue: runs before the dependency sync (overlaps producer tail).
    if (tid < CW) {
        int m = nb + tid;
        float x = S[m], y = S[NN + m], z = S[2 * NN + m];
        float w = x * x + y * y + z * z;
        t_xy[tid] = make_ulonglong2(pk2(x, x), pk2(y, y));
        t_zw[tid] = make_ulonglong2(pk2(z, z), pk2(w, w));
    }
    float x0 = T[m0], y0 = T[MM + m0], z0 = T[2 * MM + m0];
    float x1 = T[m1], y1 = T[MM + m1], z1 = T[2 * MM + m1];
    u64 X = pk2(-2.f * x0, -2.f * x1), Y = pk2(-2.f * y0, -2.f * y1), Z = pk2(-2.f * z0, -2.f * z1);
    u64 P = pk2(x0 * x0 + y0 * y0 + z0 * z0, x1 * x1 + y1 * y1 + z1 * z1);
    cudaGridDependencySynchronize();          // g_invt ready after this
    float c1 = -g_invt[b] * L2E;
    __syncthreads();
    u64 A = 0;
#pragma unroll 8
    for (int j = 0; j < CW; j++) {
        ulonglong2 xy = t_xy[j], zw = t_zw[j];
        u64 sq = fma2(X, xy.x, fma2(Y, xy.y, fma2(Z, zw.x, add2(P, zw.y))));
        float s0, s1;
        upk2(s0, s1, sq);
        float d0 = fsqrt_a(fmaxf(s0, FEPS));
        float d1 = fsqrt_a(fmaxf(s1, FEPS));
        A = add2(A, ex2_f16pair(d0 * c1, d1 * c1));   // one MUFU for both exps
    }
    float a0, a1;
    upk2(a0, a1, A);
    g_colpart[b][nc][m0] = a0;
    g_colpart[b][nc][m1] = a1;
}

// ---------------- K4: main pass partials (e on f32 MUFU, h on f16x2 MUFU, PDL) ----------------
// grid (4 ntile, 32 mchunk, 8 b), 256 threads; thread owns n0, n0+256.
__global__ void k_main_part(const float* __restrict__ src, const float* __restrict__ tgt,
                            const int* __restrict__ iter) {
    int b = blockIdx.z, nt = blockIdx.x, mc = blockIdx.y, tid = threadIdx.x;
    int n0 = nt * 512 + tid, n1 = n0 + 256;
    int mb = mc * CW;
    const float* S = src + b * 3 * NN;
    const float* T = tgt + b * 3 * MM;
    __shared__ ulonglong2 t_xy[CW];
    __shared__ ulonglong2 t_zw[CW];
    __shared__ u64 t_ic[CW];
    // Pure-input prologue before the dependency sync.
    if (tid < CW) {
        int m = mb + tid;
        float x = T[m], y = T[MM + m], z = T[2 * MM + m];
        float w = x * x + y * y + z * z;
        t_xy[tid] = make_ulonglong2(pk2(x, x), pk2(y, y));
        t_zw[tid] = make_ulonglong2(pk2(z, z), pk2(w, w));
    }
    float x0 = S[n0], y0 = S[NN + n0], z0 = S[2 * NN + n0];
    float x1 = S[n1], y1 = S[NN + n1], z1 = S[2 * NN + n1];
    u64 X = pk2(-2.f * x0, -2.f * x1), Y = pk2(-2.f * y0, -2.f * y1), Z = pk2(-2.f * z0, -2.f * z1);
    u64 P = pk2(x0 * x0 + y0 * y0 + z0 * z0, x1 * x1 + y1 * y1 + z1 * z1);
    float invT = fex2((float)(*iter - 1));      // input read — safe pre-sync
    cudaGridDependencySynchronize();            // g_colpart / g_invt ready after this
    if (tid < CW) {
        int m = mb + tid;
        float cs = 0.0f;
#pragma unroll
        for (int nc = 0; nc < NC; nc++) cs += g_colpart[b][nc][m];
        float ic = frcp_a(cs);
        t_ic[tid] = pk2(ic, ic);
    }
    float c1 = -g_invt[b] * L2E;
    float ch = 2.0f * c1 - invT * L2E;          // e^2 * f = exp2(ch * d)
    __syncthreads();
    u64 R = 0, Sv = 0, G = 0, C0a = 0, C1a = 0, C2a = 0;
#pragma unroll 4
    for (int j = 0; j < CW; j++) {
        ulonglong2 xy = t_xy[j], zw = t_zw[j];
        u64 ic = t_ic[j];
        u64 sq = fma2(X, xy.x, fma2(Y, xy.y, fma2(Z, zw.x, add2(P, zw.y))));
        float q0, q1;
        upk2(q0, q1, sq);
        float d0 = fsqrt_a(fmaxf(q0, FEPS));
        float d1 = fsqrt_a(fmaxf(q1, FEPS));
        float e0 = fex2(d0 * c1), e1 = fex2(d1 * c1);    // softmax numerator (f32 MUFU)
        u64 h2 = ex2_f16pair(d0 * ch, d1 * ch);          // e^2*exp(-d/T), one f16x2 MUFU
        u64 e2 = pk2(e0, e1);
        u64 w = mul2(mul2(e2, e2), ic);
        R = add2(R, e2);
        Sv = add2(Sv, w);
        G = fma2(h2, ic, G);
        C0a = fma2(w, xy.x, C0a);
        C1a = fma2(w, xy.y, C1a);
        C2a = fma2(w, zw.x, C2a);
    }
    float v0, v1;
    upk2(v0, v1, R);   g_part6[b][mc][0][n0] = v0; g_part6[b][mc][0][n1] = v1;
    upk2(v0, v1, Sv);  g_part6[b][mc][1][n0] = v0; g_part6[b][mc][1][n1] = v1;
    upk2(v0, v1, G);   g_part6[b][mc][2][n0] = v0; g_part6[b][mc][2][n1] = v1;
    upk2(v0, v1, C0a); g_part6[b][mc][3][n0] = v0; g_part6[b][mc][3][n1] = v1;
    upk2(v0, v1, C1a); g_part6[b][mc][4][n0] = v0; g_part6[b][mc][4][n1] = v1;
    upk2(v0, v1, C2a); g_part6[b][mc][5][n0] = v0; g_part6[b][mc][5][n1] = v1;
}

// ---------------- 3x3 Procrustes SVD (double, one thread) ----------------
__device__ void svd3_kabsch(const double H[3][3], double R[3][3]) {
    double A[3][3];
    for (int i = 0; i < 3; i++)
        for (int j = 0; j < 3; j++) {
            double s = 0;
            for (int k = 0; k < 3; k++) s += H[k][i] * H[k][j];
            A[i][j] = s;
        }
    double V[3][3] = {{1,0,0},{0,1,0},{0,0,1}};
    const int PQ[3][2] = {{0,1},{0,2},{1,2}};
    for (int sweep = 0; sweep < 30; sweep++) {
        double off = fabs(A[0][1]) + fabs(A[0][2]) + fabs(A[1][2]);
        if (off < 1e-30) break;
        for (int r = 0; r < 3; r++) {
            int p = PQ[r][0], q = PQ[r][1];
            double apq = A[p][q];
            if (fabs(apq) < 1e-300) continue;
            double theta = (A[q][q] - A[p][p]) / (2.0 * apq);
            double t = ((theta >= 0.0) ? 1.0 : -1.0) / (fabs(theta) + sqrt(1.0 + theta * theta));
            double c = 1.0 / sqrt(1.0 + t * t), s = t * c;
            for (int k = 0; k < 3; k++) {
                double akp = A[k][p], akq = A[k][q];
                A[k][p] = c * akp - s * akq;
                A[k][q] = s * akp + c * akq;
            }
            for (int k = 0; k < 3; k++) {
                double apk = A[p][k], aqk = A[q][k];
                A[p][k] = c * apk - s * aqk;
                A[q][k] = s * apk + c * aqk;
            }
            for (int k = 0; k < 3; k++) {
                double vkp = V[k][p], vkq = V[k][q];
                V[k][p] = c * vkp - s * vkq;
                V[k][q] = s * vkp + c * vkq;
            }
        }
    }
    int idx[3] = {0, 1, 2};
    double lam[3] = {A[0][0], A[1][1], A[2][2]};
    for (int i = 0; i < 2; i++)
        for (int j = i + 1; j < 3; j++)
            if (lam[idx[j]] > lam[idx[i]]) { int t = idx[i]; idx[i] = idx[j]; idx[j] = t; }
    double U[3][3], Vs[3][3];
    for (int i = 0; i < 3; i++) {
        int id = idx[i];
        double v0 = V[0][id], v1 = V[1][id], v2 = V[2][id];
        double u0 = H[0][0]*v0 + H[0][1]*v1 + H[0][2]*v2;
        double u1 = H[1][0]*v0 + H[1][1]*v1 + H[1][2]*v2;
        double u2 = H[2][0]*v0 + H[2][1]*v1 + H[2][2]*v2;
        double sig = sqrt(u0*u0 + u1*u1 + u2*u2);
        sig = (sig > 1e-300) ? sig : 1e-300;
        U[0][i] = u0 / sig; U[1][i] = u1 / sig; U[2][i] = u2 / sig;
        Vs[0][i] = v0; Vs[1][i] = v1; Vs[2][i] = v2;
    }
    double detH = H[0][0]*(H[1][1]*H[2][2] - H[1][2]*H[2][1])
                - H[0][1]*(H[1][0]*H[2][2] - H[1][2]*H[2][0])
                + H[0][2]*(H[1][0]*H[2][1] - H[1][1]*H[2][0]);
    double flip = (detH < 0.0) ? -1.0 : 1.0;
    Vs[0][2] *= flip; Vs[1][2] *= flip; Vs[2][2] *= flip;
    for (int r = 0; r < 3; r++)
        for (int c = 0; c < 3; c++)
            R[r][c] = Vs[r][0]*U[c][0] + Vs[r][1]*U[c][1] + Vs[r][2]*U[c][2];
}

// ---------------- K5: finalize per-n + H partials + (last block per batch) SVD (PDL) ----------------
// grid (32 ntile, 8 b), 64 threads (2 warps); thread owns one n.
// out: [0,72) R, [72,96) t, [96,...) src_corr
__global__ void k_finalize(const float* __restrict__ src, float* __restrict__ out) {
    cudaGridDependencySynchronize();
    int nt = blockIdx.x, b = blockIdx.y, tid = threadIdx.x;
    int lane = tid & 31, wrp = tid >> 5;
    int n = nt * 64 + tid;
    const float* S = src + b * 3 * NN;
    float* corr = out + 96 + b * 3 * NN;
    float Rn = 0.f, S2 = 0.f, G = 0.f, c0 = 0.f, c1 = 0.f, c2 = 0.f;
#pragma unroll 8
    for (int mc = 0; mc < NC; mc++) {
        Rn += g_part6[b][mc][0][n];
        S2 += g_part6[b][mc][1][n];
        G  += g_part6[b][mc][2][n];
        c0 += g_part6[b][mc][3][n];
        c1 += g_part6[b][mc][4][n];
        c2 += g_part6[b][mc][5][n];
    }
    float g = G / Rn;
    float invden = 1.0f / (S2 + FEPS * Rn);
    float cx = c0 * invden, cy = c1 * invden, cz = c2 * invden;
    corr[n]          = cx;
    corr[NN + n]     = cy;
    corr[2 * NN + n] = cz;
    float sx = S[n], sy = S[NN + n], sz = S[2 * NN + n];
    float acc[16];
    acc[0] = g;
    acc[1] = g * sx;  acc[2] = g * sy;  acc[3] = g * sz;
    acc[4] = g * cx;  acc[5] = g * cy;  acc[6] = g * cz;
    acc[7]  = g * sx * cx; acc[8]  = g * sx * cy; acc[9]  = g * sx * cz;
    acc[10] = g * sy * cx; acc[11] = g * sy * cy; acc[12] = g * sy * cz;
    acc[13] = g * sz * cx; acc[14] = g * sz * cy; acc[15] = g * sz * cz;
#pragma unroll
    for (int k = 0; k < 16; k++) {
#pragma unroll
        for (int off = 16; off > 0; off >>= 1)
            acc[k] += __shfl_down_sync(0xFFFFFFFFu, acc[k], off);
    }
    __shared__ float red[2][16];
    if (lane == 0) {
#pragma unroll
        for (int k = 0; k < 16; k++) red[wrp][k] = acc[k];
    }
    __syncthreads();
    if (tid < 16) g_hpart[b][nt][tid] = red[0][tid] + red[1][tid];

    // ---- last block per batch (32 blocks): sum tiles + SVD ----
    __shared__ unsigned s_last;
    __shared__ float tot_sh[16];
    __syncthreads();
    if (tid == 0) {
        __threadfence();
        unsigned old = atomicAdd(&g_cnt[b], 1u);
        s_last = ((old & 31u) == 31u) ? 1u : 0u;
    }
    __syncthreads();
    if (!s_last) return;
    __threadfence();
    if (tid < 16) {
        float s = 0.f;
#pragma unroll
        for (int t = 0; t < 32; t++) s += g_hpart[b][t][tid];
        tot_sh[tid] = s;
    }
    __syncthreads();
    if (tid != 0) return;
    float tot[16];
#pragma unroll
    for (int k = 0; k < 16; k++) tot[k] = tot_sh[k];
    double g1 = tot[0];
    double Ss[3] = {tot[1], tot[2], tot[3]};
    double Sc[3] = {tot[4], tot[5], tot[6]};
    double Mm[3][3] = {{tot[7], tot[8], tot[9]},
                       {tot[10], tot[11], tot[12]},
                       {tot[13], tot[14], tot[15]}};
    double gsum = g1 + 1e-12;
    double sm[3], cm[3];
    for (int d = 0; d < 3; d++) { sm[d] = Ss[d] / gsum; cm[d] = Sc[d] / gsum; }
    double H[3][3];
    for (int r = 0; r < 3; r++)
        for (int c = 0; c < 3; c++)
            H[r][c] = Mm[r][c] - sm[r] * Sc[c] - cm[c] * Ss[r] + sm[r] * cm[c] * g1;
    H[0][0] += 1e-12; H[1][1] += 2e-12; H[2][2] += 3e-12;
    double R3[3][3];
    svd3_kabsch(H, R3);
    for (int r = 0; r < 3; r++)
        for (int c = 0; c < 3; c++)
            out[b * 9 + r * 3 + c] = (float)R3[r][c];
    for (int d = 0; d < 3; d++)
        out[72 + b * 3 + d] =
            (float)(-(R3[d][0] * sm[0] + R3[d][1] * sm[1] + R3[d][2] * sm[2]) + cm[d]);
}

// ---------------- launch (PDL chain) ----------------
static inline void launch_pdl(void* fn, dim3 grid, dim3 block,
                              void** args) {
    cudaLaunchConfig_t cfg = {};
    cudaLaunchAttribute attr[1];
    attr[0].id = cudaLaunchAttributeProgrammaticStreamSerialization;
    attr[0].val.programmaticStreamSerializationAllowed = 1;
    cfg.gridDim = grid;
    cfg.blockDim = block;
    cfg.attrs = attr;
    cfg.numAttrs = 1;
    cfg.stream = 0;
    cudaLaunchKernelExC(&cfg, fn, args);
}

extern "C" void kernel_launch(void* const* d_in, const int* in_sizes, int n_in,
                              void* d_out, int out_size) {
    const float* src = (const float*)d_in[0];
    const float* tgt = (const float*)d_in[1];
    const int* iter = (const int*)d_in[2];
    float* out = (float*)d_out;

    k_alpha_part<<<dim3(4, NC, 8), 256>>>(src);

    {   void* args[] = {};
        launch_pdl((void*)k_alpha_comb, dim3(8), dim3(256), args); }
    {   void* args[] = {(void*)&src, (void*)&tgt};
        launch_pdl((void*)k_colsum_part, dim3(4, NC, 8), dim3(256), args); }
    {   void* args[] = {(void*)&src, (void*)&tgt, (void*)&iter};
        launch_pdl((void*)k_main_part, dim3(4, NC, 8), dim3(256), args); }
    {   void* args[] = {(void*)&src, (void*)&out};
        launch_pdl((void*)k_finalize, dim3(32, 8), dim3(64), args); }
}